// round 16
// baseline (speedup 1.0000x reference)
#include <cuda_runtime.h>
#include <cstdint>

// Laplacian_22711787061657 — FINAL
// x: (32, 1, 1024, 1024) fp32. Circular 2nd difference along H and W:
//   gx[h][w] = x[h-2][w] - 2*x[h-1][w] + x[h][w]   (mod 1024)
//   gy[h][w] = x[h][w-2] - 2*x[h][w-1] + x[h][w]   (mod 1024)
//   out = clip(gx+gy, -1, 1) * 0.5, NaN(x)->1.0 on input, NaN->0 on output.
//
// Roofline-confirmed configuration (15 rounds of measurement):
//   - rolling-register H walk (rows h-1/h-2 in registers)
//   - 256-bit LDG/STG (v8.b32) for the main stream
//   - W-neighbor: 16-byte float4 at the tail of the w-8 group (same cache
//     line as a neighbor thread's main load -> L1 hit; only last 2 lanes used)
//   - CHUNK=32, grid 1024 x 128 threads (~28 warps/SM sweet spot)
//   - unroll 2, default L2/store policy (all hint variants measured neutral)
// Measured: 39.2-39.6 us kernel, ~5.7 TB/s HBM, ~226 MB traffic
// = traffic/rate roofline for this access pattern on sm_103a.

#define HW 1024            // H == W == 1024
#define ROW_F8 (HW / 8)    // 128 8-float groups per row
#define CHUNK 32           // rows per block
#define NCHUNK (HW / CHUNK)

// 256-bit non-coherent load, default L2 policy
__device__ __forceinline__ void ldg256(const float* p, float* r) {
    asm("ld.global.nc.v8.b32 {%0,%1,%2,%3,%4,%5,%6,%7}, [%8];"
        : "=f"(r[0]), "=f"(r[1]), "=f"(r[2]), "=f"(r[3]),
          "=f"(r[4]), "=f"(r[5]), "=f"(r[6]), "=f"(r[7])
        : "l"(p));
}

// 128-bit non-coherent load (W-neighbor tail)
__device__ __forceinline__ float4 ldg128(const float* p) {
    float4 v;
    asm("ld.global.nc.v4.f32 {%0,%1,%2,%3}, [%4];"
        : "=f"(v.x), "=f"(v.y), "=f"(v.z), "=f"(v.w) : "l"(p));
    return v;
}

// 256-bit store, default policy
__device__ __forceinline__ void stg256(float* p, const float* r) {
    asm volatile("st.global.v8.b32 [%0], {%1,%2,%3,%4,%5,%6,%7,%8};"
                 :: "l"(p),
                    "f"(r[0]), "f"(r[1]), "f"(r[2]), "f"(r[3]),
                    "f"(r[4]), "f"(r[5]), "f"(r[6]), "f"(r[7])
                 : "memory");
}

__device__ __forceinline__ float scrub1(float v) {
    return isnan(v) ? 1.0f : v;      // remove_nan(x, 1.0)
}

__device__ __forceinline__ float finish(float gx, float gy) {
    // 0.5 * clip(gx+gy, -1, 1) == clamp(0.5*(gx+gy), -0.5, 0.5)
    float g = 0.5f * (gx + gy);
    g = fminf(0.5f, fmaxf(-0.5f, g));
    return isnan(g) ? 0.0f : g;      // remove_nan on output
}

__global__ __launch_bounds__(ROW_F8, 8)
void laplacian_kernel(const float* __restrict__ x, float* __restrict__ out) {
    const int t     = threadIdx.x;        // 8-float column group, 0..127
    const int chunk = blockIdx.x;         // 0..NCHUNK-1
    const int b     = blockIdx.y;         // image index

    const size_t img_off = (size_t)b * (HW * HW);
    const float* __restrict__ xi = x + img_off;
    float* __restrict__ oi = out + img_off;

    const int c  = t * 8;                                   // element column
    // last 4 elements of the w-8 group: elems c-4..c-1 (16B-aligned)
    const int cp4 = (((t + ROW_F8 - 1) & (ROW_F8 - 1)) * 8) + 4;

    const int h0  = chunk * CHUNK;
    const int hm2 = (h0 + HW - 2) & (HW - 1);
    const int hm1 = (h0 + HW - 1) & (HW - 1);

    float rm2[8], rm1[8];
    ldg256(xi + (size_t)hm2 * HW + c, rm2);
    ldg256(xi + (size_t)hm1 * HW + c, rm1);
    #pragma unroll
    for (int j = 0; j < 8; ++j) { rm2[j] = scrub1(rm2[j]); rm1[j] = scrub1(rm1[j]); }

    const float* __restrict__ rin  = xi + (size_t)h0 * HW;
    float*       __restrict__ rout = oi + (size_t)h0 * HW;

    #pragma unroll 2
    for (int i = 0; i < CHUNK; ++i) {
        float a[8];
        ldg256(rin + c, a);                     // elems c..c+7
        const float4 p = ldg128(rin + cp4);     // elems c-4..c-1 (L1 hit)

        #pragma unroll
        for (int j = 0; j < 8; ++j) a[j] = scrub1(a[j]);
        const float p6 = scrub1(p.z);           // elem c-2
        const float p7 = scrub1(p.w);           // elem c-1

        float g[8];
        g[0] = finish(rm2[0] - 2.0f * rm1[0] + a[0],  p6 - 2.0f * p7   + a[0]);
        g[1] = finish(rm2[1] - 2.0f * rm1[1] + a[1],  p7 - 2.0f * a[0] + a[1]);
        #pragma unroll
        for (int j = 2; j < 8; ++j)
            g[j] = finish(rm2[j] - 2.0f * rm1[j] + a[j],
                          a[j-2] - 2.0f * a[j-1] + a[j]);

        stg256(rout + c, g);

        #pragma unroll
        for (int j = 0; j < 8; ++j) { rm2[j] = rm1[j]; rm1[j] = a[j]; }
        rin  += HW;
        rout += HW;
    }
}

extern "C" void kernel_launch(void* const* d_in, const int* in_sizes, int n_in,
                              void* d_out, int out_size) {
    const float* x = (const float*)d_in[0];
    float* out = (float*)d_out;
    const int batch = in_sizes[0] / (HW * HW); // 32

    dim3 grid(NCHUNK, batch);
    dim3 block(ROW_F8);
    laplacian_kernel<<<grid, block>>>(x, out);
}

// round 17
// speedup vs baseline: 1.0336x; 1.0336x over previous
#include <cuda_runtime.h>
#include <cstdint>

// Laplacian_22711787061657 — FINAL (v13 configuration, best measured)
// x: (32, 1, 1024, 1024) fp32. Circular 2nd difference along H and W:
//   gx[h][w] = x[h-2][w] - 2*x[h-1][w] + x[h][w]   (mod 1024)
//   gy[h][w] = x[h][w-2] - 2*x[h][w-1] + x[h][w]   (mod 1024)
//   out = clip(gx+gy, -1, 1) * 0.5, NaN(x)->1.0 on input, NaN->0 on output.
//
// Roofline-confirmed across 16 rounds of measurement:
//   - rolling-register H walk: rows h-1/h-2 carried in registers
//     (zero H-direction read amplification; 2 halo rows per 32 = 6.25%)
//   - 256-bit LDG/STG (v8.b32): half the memory instructions of float4
//   - W-neighbor via full v8 load of the w-8 group (same-row neighbor
//     thread's line -> L1 hit; measured faster than float2/float4/shfl)
//   - CHUNK=32, grid 1024 x 128 threads: ~28 warps/SM sweet spot
//     (more warps -> L1tex queue contention; fewer -> MLP starvation)
//   - unroll 2 (regs 55; unroll 4 hit 64-reg cap, slower)
//   - default L2/store policy (.cs/evict_first/evict_last/.wt/partitioned
//     all measured neutral: 268 MB working set can't be pinned in 126 MB
//     L2; passive retention already saves ~43 MB/replay)
// Measured: 39.2-39.6 us kernel, ~5.7 TB/s HBM, ~225 MB traffic.
// 225 MB / 5.7 TB/s = 39.5 us -> kernel sits on its memory roofline.

#define HW 1024            // H == W == 1024
#define ROW_F8 (HW / 8)    // 128 8-float groups per row
#define CHUNK 32           // rows per block
#define NCHUNK (HW / CHUNK)

// 256-bit non-coherent load, default L2 policy
__device__ __forceinline__ void ldg256(const float* p, float* r) {
    asm("ld.global.nc.v8.b32 {%0,%1,%2,%3,%4,%5,%6,%7}, [%8];"
        : "=f"(r[0]), "=f"(r[1]), "=f"(r[2]), "=f"(r[3]),
          "=f"(r[4]), "=f"(r[5]), "=f"(r[6]), "=f"(r[7])
        : "l"(p));
}

// 256-bit store, default policy
__device__ __forceinline__ void stg256(float* p, const float* r) {
    asm volatile("st.global.v8.b32 [%0], {%1,%2,%3,%4,%5,%6,%7,%8};"
                 :: "l"(p),
                    "f"(r[0]), "f"(r[1]), "f"(r[2]), "f"(r[3]),
                    "f"(r[4]), "f"(r[5]), "f"(r[6]), "f"(r[7])
                 : "memory");
}

__device__ __forceinline__ float scrub1(float v) {
    return isnan(v) ? 1.0f : v;      // remove_nan(x, 1.0)
}

__device__ __forceinline__ float finish(float gx, float gy) {
    // 0.5 * clip(gx+gy, -1, 1) == clamp(0.5*(gx+gy), -0.5, 0.5)
    float g = 0.5f * (gx + gy);
    g = fminf(0.5f, fmaxf(-0.5f, g));
    return isnan(g) ? 0.0f : g;      // remove_nan on output
}

__global__ __launch_bounds__(ROW_F8, 8)
void laplacian_kernel(const float* __restrict__ x, float* __restrict__ out) {
    const int t     = threadIdx.x;        // 8-float column group, 0..127
    const int chunk = blockIdx.x;         // 0..NCHUNK-1
    const int b     = blockIdx.y;         // image index

    const size_t img_off = (size_t)b * (HW * HW);
    const float* __restrict__ xi = x + img_off;
    float* __restrict__ oi = out + img_off;

    const int c  = t * 8;                                   // element column
    const int cp = (((t + ROW_F8 - 1) & (ROW_F8 - 1)) * 8); // group at w-8

    const int h0  = chunk * CHUNK;
    const int hm2 = (h0 + HW - 2) & (HW - 1);
    const int hm1 = (h0 + HW - 1) & (HW - 1);

    float rm2[8], rm1[8];
    ldg256(xi + (size_t)hm2 * HW + c, rm2);
    ldg256(xi + (size_t)hm1 * HW + c, rm1);
    #pragma unroll
    for (int j = 0; j < 8; ++j) { rm2[j] = scrub1(rm2[j]); rm1[j] = scrub1(rm1[j]); }

    const float* __restrict__ rin  = xi + (size_t)h0 * HW;
    float*       __restrict__ rout = oi + (size_t)h0 * HW;

    #pragma unroll 2
    for (int i = 0; i < CHUNK; ++i) {
        float a[8], p[8];
        ldg256(rin + c,  a);   // elems c..c+7
        ldg256(rin + cp, p);   // elems c-8..c-1 (L1 hit; only [6],[7] used)

        #pragma unroll
        for (int j = 0; j < 8; ++j) a[j] = scrub1(a[j]);
        const float p6 = scrub1(p[6]);
        const float p7 = scrub1(p[7]);

        float g[8];
        g[0] = finish(rm2[0] - 2.0f * rm1[0] + a[0],  p6 - 2.0f * p7   + a[0]);
        g[1] = finish(rm2[1] - 2.0f * rm1[1] + a[1],  p7 - 2.0f * a[0] + a[1]);
        #pragma unroll
        for (int j = 2; j < 8; ++j)
            g[j] = finish(rm2[j] - 2.0f * rm1[j] + a[j],
                          a[j-2] - 2.0f * a[j-1] + a[j]);

        stg256(rout + c, g);

        #pragma unroll
        for (int j = 0; j < 8; ++j) { rm2[j] = rm1[j]; rm1[j] = a[j]; }
        rin  += HW;
        rout += HW;
    }
}

extern "C" void kernel_launch(void* const* d_in, const int* in_sizes, int n_in,
                              void* d_out, int out_size) {
    const float* x = (const float*)d_in[0];
    float* out = (float*)d_out;
    const int batch = in_sizes[0] / (HW * HW); // 32

    dim3 grid(NCHUNK, batch);
    dim3 block(ROW_F8);
    laplacian_kernel<<<grid, block>>>(x, out);
}